// round 4
// baseline (speedup 1.0000x reference)
#include <cuda_runtime.h>
#include <cuda_bf16.h>

// Problem constants (fixed by the reference)
#define B 16
#define S 4096
#define H 768
#define NUM_WORDS 2048          // S/2
#define H4 (H / 4)              // 192 float4 lanes per row
#define W 16                    // words per block
#define G 8                     // tokens batch-loaded per group (MLP depth)
#define CHUNKS (NUM_WORDS / W)  // 128

// Per-(b,word) token-run boundaries. __device__ globals are zero-initialized;
// the boundary kernel only writes entries for words that actually occur, so
// absent words keep start == end == 0 -> count 0 -> zero output. This makes
// kernel B need no wmax lookup and no clamping.
__device__ int g_start[B * NUM_WORDS];
__device__ int g_end[B * NUM_WORDS];

// Kernel A: smem-tiled neighbor compare. word_ids row: wrow[0] = -1,
// wrow[S-1] = -1, non-decreasing contiguous from 0 in between.
__global__ __launch_bounds__(256) void boundary_kernel(
    const int* __restrict__ word_ids)   // [B, S]
{
    __shared__ int s[258];
    const int b    = blockIdx.y;
    const int base = blockIdx.x * 256;               // covers positions base..base+257
    const int* __restrict__ wrow = word_ids + b * S;

    for (int idx = threadIdx.x; idx < 258; idx += 256) {
        int p = base + idx;
        s[idx] = (p < S) ? wrow[p] : -1;
    }
    __syncthreads();

    const int i = base + threadIdx.x + 1;            // 1 .. S-2
    if (i <= S - 2) {
        const int w  = s[threadIdx.x + 1];
        const int wp = s[threadIdx.x];
        const int wn = s[threadIdx.x + 2];
        if (wp != w) g_start[b * NUM_WORDS + w] = i;
        if (wn != w) g_end[b * NUM_WORDS + w]   = i + 1;
    }
}

// Kernel B: one block per (batch, chunk of W consecutive words). The chunk's
// tokens form one contiguous run [s0, e_last). Stream it in groups of G
// front-batched float4 loads; route tokens to words via uniform smem ends.
__global__ __launch_bounds__(H4) void word_mean_kernel(
    const float* __restrict__ hidden,   // [B, S, H]
    float*       __restrict__ out)      // [B, NUM_WORDS, H]
{
    const int blk = blockIdx.x;
    const int b   = blk / CHUNKS;
    const int wc  = blk % CHUNKS;
    const int w0  = wc * W;
    const int tid = threadIdx.x;        // 0..191

    __shared__ int s_end[W];
    __shared__ int s_s0;
    if (tid < W)  s_end[tid] = g_end[b * NUM_WORDS + w0 + tid];
    if (tid == W) s_s0 = g_start[b * NUM_WORDS + w0];
    __syncthreads();

    // Last token of the last PRESENT word in this chunk (absent ends are 0,
    // present ends strictly increase).
    int e_last = 0;
    #pragma unroll
    for (int k = 0; k < W; ++k) e_last = max(e_last, s_end[k]);
    const int s0 = s_s0;

    const float4* __restrict__ hs4 =
        reinterpret_cast<const float4*>(hidden) + (size_t)b * S * H4 + tid;
    float4* __restrict__ outBase =
        reinterpret_cast<float4*>(out) + (size_t)(b * NUM_WORDS + w0) * H4 + tid;

    int k = 0;
    int e_cur = s_end[0];
    int s_cur = s0;
    float4 acc = make_float4(0.f, 0.f, 0.f, 0.f);

    for (int t = s0; t < e_last; t += G) {
        // Batch-issue up to G independent coalesced float4 loads.
        float4 v[G];
        #pragma unroll
        for (int j = 0; j < G; ++j)
            if (t + j < e_last) v[j] = hs4[(size_t)(t + j) * H4];

        // Route tokens to word accumulators (boundaries uniform across warp).
        #pragma unroll
        for (int j = 0; j < G; ++j) {
            if (t + j < e_last) {
                if (t + j == e_cur) {     // word k complete -> emit mean
                    const int c = e_cur - s_cur;
                    const float inv = __fdividef(1.0f, (float)(c > 0 ? c : 1));
                    float4 r;
                    r.x = acc.x * inv; r.y = acc.y * inv;
                    r.z = acc.z * inv; r.w = acc.w * inv;
                    outBase[k * H4] = r;
                    s_cur = e_cur;
                    ++k;
                    e_cur = s_end[k];
                    acc = make_float4(0.f, 0.f, 0.f, 0.f);
                }
                acc.x += v[j].x; acc.y += v[j].y;
                acc.z += v[j].z; acc.w += v[j].w;
            }
        }
    }

    // Emit remaining words: the last present word (its end == e_last is never
    // reached inside the loop) plus trailing absent words (end 0 -> count<=0
    // with acc already zeroed -> writes zeros).
    while (k < W) {
        const int c = e_cur - s_cur;
        const float inv = __fdividef(1.0f, (float)(c > 0 ? c : 1));
        float4 r;
        r.x = acc.x * inv; r.y = acc.y * inv;
        r.z = acc.z * inv; r.w = acc.w * inv;
        outBase[k * H4] = r;
        s_cur = e_cur;
        ++k;
        if (k < W) e_cur = s_end[k];
        acc = make_float4(0.f, 0.f, 0.f, 0.f);
    }
}

extern "C" void kernel_launch(void* const* d_in, const int* in_sizes, int n_in,
                              void* d_out, int out_size)
{
    const float* hidden   = (const float*)d_in[0];  // [B,S,H] float32
    const int*   word_ids = (const int*)d_in[1];    // [B,S] int32
    float*       out      = (float*)d_out;          // [B,NUM_WORDS,H] float32

    (void)in_sizes; (void)n_in; (void)out_size;

    dim3 gridA((S - 2 + 255) / 256, B);             // 16 x 16
    boundary_kernel<<<gridA, 256>>>(word_ids);
    word_mean_kernel<<<B * CHUNKS, H4>>>(hidden, out);
}

// round 7
// speedup vs baseline: 1.0401x; 1.0401x over previous
#include <cuda_runtime.h>
#include <cuda_bf16.h>
#include <cuda_pipeline.h>
#include <cstdint>

// Problem constants (fixed by the reference)
#define B 16
#define S 4096
#define H 768
#define NUM_WORDS 2048          // S/2
#define H4 (H / 4)              // 192 float4 lanes per row
#define W 16                    // words per block
#define T 6                     // tokens per pipeline stage
#define CHUNKS (NUM_WORDS / W)  // 128
#define STG_F4 (T * H4)         // float4 elements per stage (1152 = 18KB)

// Per-(b,word) token-run boundaries. __device__ globals are zero-initialized;
// the boundary kernel only writes entries for words that occur, so absent
// words keep start == end == 0 -> empty run -> zero output.
__device__ int g_start[B * NUM_WORDS];
__device__ int g_end[B * NUM_WORDS];

// Kernel A: smem-tiled neighbor compare. word_ids row: wrow[0] = -1,
// wrow[S-1] = -1, non-decreasing contiguous from 0 in between.
__global__ __launch_bounds__(256) void boundary_kernel(
    const int* __restrict__ word_ids)   // [B, S]
{
    __shared__ int s[258];
    const int b    = blockIdx.y;
    const int base = blockIdx.x * 256;
    const int* __restrict__ wrow = word_ids + b * S;

    for (int idx = threadIdx.x; idx < 258; idx += 256) {
        int p = base + idx;
        s[idx] = (p < S) ? wrow[p] : -1;
    }
    __syncthreads();

    const int i = base + threadIdx.x + 1;            // 1 .. S-2
    if (i <= S - 2) {
        const int w  = s[threadIdx.x + 1];
        const int wp = s[threadIdx.x];
        const int wn = s[threadIdx.x + 2];
        if (wp != w) g_start[b * NUM_WORDS + w] = i;
        if (wn != w) g_end[b * NUM_WORDS + w]   = i + 1;
    }
}

// Kernel B: one block per (batch, chunk of W consecutive words). The chunk's
// tokens form one contiguous run [s0, e_last). Stream it through a 2-stage
// cp.async smem pipeline; route tokens to words via the (R4-proven) uniform
// smem boundary table.
__global__ __launch_bounds__(H4) void word_mean_kernel(
    const float* __restrict__ hidden,   // [B, S, H]
    float*       __restrict__ out)      // [B, NUM_WORDS, H]
{
    __shared__ float4 s_buf[2][STG_F4];     // 36 KB
    __shared__ int s_end[W];
    __shared__ int s_s0;

    const int blk = blockIdx.x;
    const int b   = blk / CHUNKS;
    const int wc  = blk % CHUNKS;
    const int w0  = wc * W;
    const int tid = threadIdx.x;            // 0..191

    if (tid < W)  s_end[tid] = g_end[b * NUM_WORDS + w0 + tid];
    if (tid == W) s_s0 = g_start[b * NUM_WORDS + w0];
    __syncthreads();

    // End of last present word (absent ends are 0, present strictly increase).
    int e_last = 0;
    #pragma unroll
    for (int k = 0; k < W; ++k) e_last = max(e_last, s_end[k]);
    const int s0 = s_s0;

    float4* __restrict__ outBase =
        reinterpret_cast<float4*>(out) + (size_t)(b * NUM_WORDS + w0) * H4 + tid;

    const int n_tok = e_last - s0;
    if (n_tok <= 0) {
        const float4 z = make_float4(0.f, 0.f, 0.f, 0.f);
        #pragma unroll
        for (int k = 0; k < W; ++k) outBase[k * H4] = z;
        return;
    }

    const float4* __restrict__ src =
        reinterpret_cast<const float4*>(hidden) + ((size_t)b * S + s0) * H4;
    const int total_f4 = n_tok * H4;
    const int n_stages = (n_tok + T - 1) / T;

    // ---- issue stage 0 ----
    #pragma unroll
    for (int i = 0; i < T; ++i) {
        const int idx = i * H4 + tid;
        if (idx < total_f4)
            __pipeline_memcpy_async(&s_buf[0][idx], &src[idx], sizeof(float4));
    }
    __pipeline_commit();

    int k = 0;
    int e_cur = s_end[0];
    int s_cur = s0;
    float4 acc = make_float4(0.f, 0.f, 0.f, 0.f);

    for (int s = 0; s < n_stages; ++s) {
        if (s + 1 < n_stages) {
            // prefetch stage s+1 into the other buffer
            float4* dst = s_buf[(s + 1) & 1];
            const int base = (s + 1) * STG_F4;
            #pragma unroll
            for (int i = 0; i < T; ++i) {
                const int idx = i * H4 + tid;
                const int g   = base + idx;
                if (g < total_f4)
                    __pipeline_memcpy_async(&dst[idx], &src[g], sizeof(float4));
            }
            __pipeline_commit();
            __pipeline_wait_prior(1);
        } else {
            __pipeline_wait_prior(0);
        }
        __syncthreads();

        const float4* __restrict__ buf = s_buf[s & 1];
        #pragma unroll
        for (int j = 0; j < T; ++j) {
            const int t = s0 + s * T + j;
            if (t < e_last) {               // uniform across block
                const float4 v = buf[j * H4 + tid];
                if (t == e_cur) {           // word k complete -> emit mean
                    const int c = e_cur - s_cur;
                    const float inv = __fdividef(1.0f, (float)(c > 0 ? c : 1));
                    float4 r;
                    r.x = acc.x * inv; r.y = acc.y * inv;
                    r.z = acc.z * inv; r.w = acc.w * inv;
                    outBase[k * H4] = r;
                    s_cur = e_cur;
                    ++k;
                    e_cur = s_end[k < W ? k : W - 1];
                    acc = make_float4(0.f, 0.f, 0.f, 0.f);
                }
                acc.x += v.x; acc.y += v.y;
                acc.z += v.z; acc.w += v.w;
            }
        }
        __syncthreads();   // protect buf[s&1] before stage s+2 overwrites it
    }

    // Emit remaining words: last present word (its end == e_last is never
    // reached inside the loop) plus trailing absent words (count <= 0 with
    // acc zeroed -> writes zeros).
    while (k < W) {
        const int c = e_cur - s_cur;
        const float inv = __fdividef(1.0f, (float)(c > 0 ? c : 1));
        float4 r;
        r.x = acc.x * inv; r.y = acc.y * inv;
        r.z = acc.z * inv; r.w = acc.w * inv;
        outBase[k * H4] = r;
        s_cur = e_cur;
        ++k;
        if (k < W) e_cur = s_end[k];
        acc = make_float4(0.f, 0.f, 0.f, 0.f);
    }
}

extern "C" void kernel_launch(void* const* d_in, const int* in_sizes, int n_in,
                              void* d_out, int out_size)
{
    const float* hidden   = (const float*)d_in[0];  // [B,S,H] float32
    const int*   word_ids = (const int*)d_in[1];    // [B,S] int32
    float*       out      = (float*)d_out;          // [B,NUM_WORDS,H] float32

    (void)in_sizes; (void)n_in; (void)out_size;

    dim3 gridA((S - 2 + 255) / 256, B);             // 16 x 16
    boundary_kernel<<<gridA, 256>>>(word_ids);
    word_mean_kernel<<<B * CHUNKS, H4>>>(hidden, out);
}